// round 1
// baseline (speedup 1.0000x reference)
#include <cuda_runtime.h>
#include <math.h>

// Problem constants
#define BB   32
#define SS   100
#define DD   256
#define HH   4
#define DK_  64
#define LL   3
#define MM   (BB*SS)      // 3200
#define DFF_ 1024
#define NOUT 50001

// ---------------- scratch (no allocation allowed -> device globals) ----------------
__device__ float g_h[MM*DD];
__device__ float g_temb[MM*DD];
__device__ float g_hn[MM*DD];
__device__ float g_q[MM*DD];
__device__ float g_k1[MM*DD];
__device__ float g_k2[MM*DD];
__device__ float g_v[MM*DD];
__device__ float g_ctx[MM*DD];
__device__ float g_ffn[MM*DFF_];

// ---------------- embedding + time embedding ----------------
__global__ void embed_kernel(const int* __restrict__ x, const float* __restrict__ times,
                             const float* __restrict__ token_emb, const float* __restrict__ pos_emb,
                             const float* __restrict__ sel_w, const float* __restrict__ sel_b,
                             const float* __restrict__ time_w, const float* __restrict__ time_b,
                             const float* __restrict__ per_w, const float* __restrict__ per_b)
{
    int bs = blockIdx.x;           // 0..3199
    int s  = bs % SS;
    int d  = threadIdx.x;          // 0..255
    __shared__ float g[64];
    float tval = times[bs];
    if (d < 64) {
        float t = tval * (1.0f/180.0f) * sel_w[d] + sel_b[d];
        g[d] = 1.0f - tanhf(t*t);
    }
    __syncthreads();
    float ang = 2.0f * 3.14159265358979323846f * tval / 24.0f;
    float sa = sinf(ang), ca = cosf(ang);
    float feat = time_b[d];
    const float* tw = time_w + d*64;
    #pragma unroll 16
    for (int j = 0; j < 64; j++) feat += g[j] * tw[j];
    float per = sa*per_w[d*2+0] + ca*per_w[d*2+1] + per_b[d];
    g_temb[bs*DD + d] = feat + per;
    int tok = x[bs];
    g_h[bs*DD + d] = token_emb[(size_t)tok*DD + d] + pos_emb[s*DD + d];
}

// ---------------- LayerNorm (torch variant: unbiased std, eps added to std) ----------------
__global__ void ln_kernel(const float* __restrict__ x, const float* __restrict__ a,
                          const float* __restrict__ b, float* __restrict__ y)
{
    int row = blockIdx.x;
    int d = threadIdx.x;
    __shared__ float red[256];
    float v = x[row*DD + d];
    red[d] = v; __syncthreads();
    #pragma unroll
    for (int s = 128; s > 0; s >>= 1) { if (d < s) red[d] += red[d+s]; __syncthreads(); }
    float mean = red[0] * (1.0f/DD);
    __syncthreads();
    float diff = v - mean;
    red[d] = diff*diff; __syncthreads();
    #pragma unroll
    for (int s = 128; s > 0; s >>= 1) { if (d < s) red[d] += red[d+s]; __syncthreads(); }
    float stdv = sqrtf(red[0] * (1.0f/(DD-1)));
    y[row*DD + d] = a[d]*diff/(stdv + 1e-6f) + b[d];
}

// ---------------- generic GEMM: C[M,N] = A[M,K] @ W[N,K]^T + bias, epi: 0=none 1=gelu 2=+res ----------------
__device__ __forceinline__ float gelu_f(float x) {
    const float c = 0.7978845608028654f;   // sqrt(2/pi)
    float x3 = x*x*x;
    return 0.5f*x*(1.0f + tanhf(c*(x + 0.044715f*x3)));
}

__global__ void gemm_kernel(const float* __restrict__ A, const float* __restrict__ W,
                            const float* __restrict__ bias, const float* __restrict__ res,
                            float* __restrict__ C, int M, int N, int K, int epi)
{
    __shared__ float As[8][128];
    __shared__ float Ws[8][128];
    int tid = threadIdx.x;              // 256 threads
    int tx = tid & 15, ty = tid >> 4;   // 16x16, each thread 8x8 micro-tile
    int row0 = blockIdx.y * 128, col0 = blockIdx.x * 128;

    float acc[8][8];
    #pragma unroll
    for (int i = 0; i < 8; i++)
        #pragma unroll
        for (int j = 0; j < 8; j++) acc[i][j] = 0.f;

    int mload = tid >> 1;               // 0..127
    int kload = (tid & 1) * 4;          // 0 or 4
    const float* Arow = A + (size_t)(row0 + mload)*K + kload;
    bool wvalid = (col0 + mload) < N;
    const float* Wrow = W + (size_t)(col0 + mload)*K + kload;

    for (int kk = 0; kk < K; kk += 8) {
        float4 fa = *(const float4*)(Arow + kk);
        As[kload+0][mload] = fa.x; As[kload+1][mload] = fa.y;
        As[kload+2][mload] = fa.z; As[kload+3][mload] = fa.w;
        float4 fw = wvalid ? *(const float4*)(Wrow + kk) : make_float4(0.f,0.f,0.f,0.f);
        Ws[kload+0][mload] = fw.x; Ws[kload+1][mload] = fw.y;
        Ws[kload+2][mload] = fw.z; Ws[kload+3][mload] = fw.w;
        __syncthreads();
        #pragma unroll
        for (int k = 0; k < 8; k++) {
            const float4* Ak = (const float4*)(&As[k][0]);
            const float4* Wk = (const float4*)(&Ws[k][0]);
            float4 a0 = Ak[ty*2], a1 = Ak[ty*2+1];
            float4 b0 = Wk[tx*2], b1 = Wk[tx*2+1];
            float av[8] = {a0.x,a0.y,a0.z,a0.w,a1.x,a1.y,a1.z,a1.w};
            float bv[8] = {b0.x,b0.y,b0.z,b0.w,b1.x,b1.y,b1.z,b1.w};
            #pragma unroll
            for (int i = 0; i < 8; i++)
                #pragma unroll
                for (int j = 0; j < 8; j++) acc[i][j] += av[i]*bv[j];
        }
        __syncthreads();
    }

    #pragma unroll
    for (int i = 0; i < 8; i++) {
        int row = row0 + ty*8 + i;
        #pragma unroll
        for (int j = 0; j < 8; j++) {
            int col = col0 + tx*8 + j;
            if (col < N) {
                float v = acc[i][j] + bias[col];
                if (epi == 1) v = gelu_f(v);
                else if (epi == 2) v += res[(size_t)row*N + col];
                C[(size_t)row*N + col] = v;
            }
        }
    }
}

// ---------------- attention: one block per (b,h) ----------------
__global__ void attn_kernel(const float* __restrict__ q, const float* __restrict__ k1,
                            const float* __restrict__ k2, const float* __restrict__ v,
                            const int* __restrict__ x, const float* __restrict__ ml,
                            float* __restrict__ ctx)
{
    extern __shared__ float sm[];
    float* qs  = sm;                 // 6400
    float* k1s = qs  + SS*DK_;
    float* k2s = k1s + SS*DK_;
    float* vs  = k2s + SS*DK_;
    float* sc  = vs  + SS*DK_;       // 10000
    int*  keep = (int*)(sc + SS*SS); // 100
    int h = blockIdx.x, b = blockIdx.y;
    int tid = threadIdx.x;
    int base = b*SS*DD + h*DK_;

    for (int idx = tid; idx < SS*DK_; idx += blockDim.x) {
        int s = idx >> 6, d = idx & 63;
        int gi = base + s*DD + d;
        qs[idx] = q[gi]; k1s[idx] = k1[gi]; k2s[idx] = k2[gi]; vs[idx] = v[gi];
    }
    if (tid < SS) keep[tid] = (x[b*SS + tid] > 0) ? 1 : 0;
    __syncthreads();

    if (tid < SS) {
        const float scale = 0.125f;  // 1/sqrt(64)
        const float* qp = qs + tid*DK_;
        float* scrow = sc + tid*SS;
        float mx = -1e30f;
        for (int k = 0; k < SS; k++) {
            const float* p1 = k1s + k*DK_;
            const float* p2 = k2s + k*DK_;
            float s1 = 0.f, s2 = 0.f;
            #pragma unroll 16
            for (int d = 0; d < DK_; d++) { s1 += qp[d]*p1[d]; s2 += qp[d]*p2[d]; }
            // masked_fill BEFORE adding time-scores (exact reference semantics)
            float s = (keep[k] ? s1*scale : -1e9f) + s2*scale;
            scrow[k] = s;
            mx = fmaxf(mx, s);
        }
        float sum = 0.f;
        for (int k = 0; k < SS; k++) { float e = expf(scrow[k] - mx); scrow[k] = e; sum += e; }
        float inv = 1.0f / sum;
        for (int k = 0; k < SS; k++) {
            float z = ml[tid*SS + k];
            float sg = 1.0f / (1.0f + expf(-z));
            scrow[k] *= inv * sg;
        }
        for (int d = 0; d < DK_; d++) {
            float acc = 0.f;
            for (int k = 0; k < SS; k++) acc += scrow[k] * vs[k*DK_ + d];
            ctx[base + tid*DD + d] = acc;
        }
    }
}

// ---------------- host launcher ----------------
extern "C" void kernel_launch(void* const* d_in, const int* in_sizes, int n_in,
                              void* d_out, int out_size)
{
    (void)in_sizes; (void)n_in; (void)out_size;
    const int*   x         = (const int*)  d_in[0];
    const float* times     = (const float*)d_in[1];
    const float* token_emb = (const float*)d_in[2];
    const float* pos_emb   = (const float*)d_in[3];
    const float* sel_w     = (const float*)d_in[4];
    const float* sel_b     = (const float*)d_in[5];
    const float* time_w    = (const float*)d_in[6];
    const float* time_b    = (const float*)d_in[7];
    const float* per_w     = (const float*)d_in[8];
    const float* per_b     = (const float*)d_in[9];
    const float* Wq        = (const float*)d_in[10];
    const float* Wk        = (const float*)d_in[11];
    const float* Wt        = (const float*)d_in[12];
    const float* Wv        = (const float*)d_in[13];
    const float* Wo        = (const float*)d_in[14];
    const float* bq        = (const float*)d_in[15];
    const float* bk        = (const float*)d_in[16];
    const float* bt        = (const float*)d_in[17];
    const float* bv        = (const float*)d_in[18];
    const float* bo        = (const float*)d_in[19];
    const float* mask_log  = (const float*)d_in[20];
    const float* ln1_a     = (const float*)d_in[21];
    const float* ln1_b     = (const float*)d_in[22];
    const float* ln2_a     = (const float*)d_in[23];
    const float* ln2_b     = (const float*)d_in[24];
    const float* ffn_w1    = (const float*)d_in[25];
    const float* ffn_b1    = (const float*)d_in[26];
    const float* ffn_w2    = (const float*)d_in[27];
    const float* ffn_b2    = (const float*)d_in[28];
    const float* out_w     = (const float*)d_in[29];
    const float* out_b     = (const float*)d_in[30];
    float* out = (float*)d_out;

    float *ph,*ptemb,*phn,*pq,*pk1,*pk2,*pv,*pctx,*pffn;
    cudaGetSymbolAddress((void**)&ph,    g_h);
    cudaGetSymbolAddress((void**)&ptemb, g_temb);
    cudaGetSymbolAddress((void**)&phn,   g_hn);
    cudaGetSymbolAddress((void**)&pq,    g_q);
    cudaGetSymbolAddress((void**)&pk1,   g_k1);
    cudaGetSymbolAddress((void**)&pk2,   g_k2);
    cudaGetSymbolAddress((void**)&pv,    g_v);
    cudaGetSymbolAddress((void**)&pctx,  g_ctx);
    cudaGetSymbolAddress((void**)&pffn,  g_ffn);

    const int attn_smem = (SS*DK_*4 + SS*SS)*(int)sizeof(float) + SS*(int)sizeof(int); // 142,800 B
    cudaFuncSetAttribute(attn_kernel, cudaFuncAttributeMaxDynamicSharedMemorySize, attn_smem);

    embed_kernel<<<MM, 256>>>(x, times, token_emb, pos_emb, sel_w, sel_b,
                              time_w, time_b, per_w, per_b);

    dim3 gD(2, 25);      // N=256
    dim3 gF(8, 25);      // N=1024
    for (int l = 0; l < LL; l++) {
        ln_kernel<<<MM, 256>>>(ph, ln1_a + l*DD, ln1_b + l*DD, phn);
        gemm_kernel<<<gD, 256>>>(phn,   Wq + (size_t)l*DD*DD, bq + l*DD, nullptr, pq,  MM, DD, DD, 0);
        gemm_kernel<<<gD, 256>>>(phn,   Wk + (size_t)l*DD*DD, bk + l*DD, nullptr, pk1, MM, DD, DD, 0);
        gemm_kernel<<<gD, 256>>>(ptemb, Wt + (size_t)l*DD*DD, bt + l*DD, nullptr, pk2, MM, DD, DD, 0);
        gemm_kernel<<<gD, 256>>>(phn,   Wv + (size_t)l*DD*DD, bv + l*DD, nullptr, pv,  MM, DD, DD, 0);
        attn_kernel<<<dim3(HH, BB), 128, attn_smem>>>(pq, pk1, pk2, pv, x,
                                                      mask_log + l*SS*SS, pctx);
        gemm_kernel<<<gD, 256>>>(pctx, Wo + (size_t)l*DD*DD, bo + l*DD, ph, ph, MM, DD, DD, 2);
        ln_kernel<<<MM, 256>>>(ph, ln2_a + l*DD, ln2_b + l*DD, phn);
        gemm_kernel<<<gF, 256>>>(phn,  ffn_w1 + (size_t)l*DFF_*DD, ffn_b1 + l*DFF_, nullptr, pffn, MM, DFF_, DD, 1);
        gemm_kernel<<<gD, 256>>>(pffn, ffn_w2 + (size_t)l*DD*DFF_, ffn_b2 + l*DD,  ph,      ph,   MM, DD, DFF_, 2);
    }
    gemm_kernel<<<dim3(391, 25), 256>>>(ph, out_w, out_b, nullptr, out, MM, NOUT, DD, 0);
}

// round 2
// speedup vs baseline: 1.2776x; 1.2776x over previous
#include <cuda_runtime.h>
#include <mma.h>
#include <math.h>
using namespace nvcuda;

// Problem constants
#define BB   32
#define SS   100
#define DD   256
#define HH   4
#define DK_  64
#define LL   3
#define MM   (BB*SS)      // 3200
#define DFF_ 1024
#define NOUT 50001

// ---------------- scratch (no allocation allowed -> device globals) ----------------
__device__ float g_h[MM*DD];
__device__ float g_temb[MM*DD];
__device__ float g_hn[MM*DD];
__device__ float g_q[MM*DD];
__device__ float g_k1[MM*DD];
__device__ float g_k2[MM*DD];
__device__ float g_v[MM*DD];
__device__ float g_ctx[MM*DD];
__device__ float g_ffn[MM*DFF_];
__device__ float g_tmp[MM*DD];

// ---------------- embedding + time embedding ----------------
__global__ void embed_kernel(const int* __restrict__ x, const float* __restrict__ times,
                             const float* __restrict__ token_emb, const float* __restrict__ pos_emb,
                             const float* __restrict__ sel_w, const float* __restrict__ sel_b,
                             const float* __restrict__ time_w, const float* __restrict__ time_b,
                             const float* __restrict__ per_w, const float* __restrict__ per_b)
{
    int bs = blockIdx.x;           // 0..3199
    int s  = bs % SS;
    int d  = threadIdx.x;          // 0..255
    __shared__ float g[64];
    float tval = times[bs];
    if (d < 64) {
        float t = tval * (1.0f/180.0f) * sel_w[d] + sel_b[d];
        g[d] = 1.0f - tanhf(t*t);
    }
    __syncthreads();
    float ang = 2.0f * 3.14159265358979323846f * tval / 24.0f;
    float sa = sinf(ang), ca = cosf(ang);
    float feat = time_b[d];
    const float* tw = time_w + d*64;
    #pragma unroll 16
    for (int j = 0; j < 64; j++) feat += g[j] * tw[j];
    float per = sa*per_w[d*2+0] + ca*per_w[d*2+1] + per_b[d];
    g_temb[bs*DD + d] = feat + per;
    int tok = x[bs];
    g_h[bs*DD + d] = token_emb[(size_t)tok*DD + d] + pos_emb[s*DD + d];
}

// ---------------- LayerNorm (torch variant: unbiased std, eps added to std) ----------------
__global__ void ln_kernel(const float* __restrict__ x, const float* __restrict__ a,
                          const float* __restrict__ b, float* __restrict__ y)
{
    int row = blockIdx.x;
    int d = threadIdx.x;
    __shared__ float red[256];
    float v = x[row*DD + d];
    red[d] = v; __syncthreads();
    #pragma unroll
    for (int s = 128; s > 0; s >>= 1) { if (d < s) red[d] += red[d+s]; __syncthreads(); }
    float mean = red[0] * (1.0f/DD);
    __syncthreads();
    float diff = v - mean;
    red[d] = diff*diff; __syncthreads();
    #pragma unroll
    for (int s = 128; s > 0; s >>= 1) { if (d < s) red[d] += red[d+s]; __syncthreads(); }
    float stdv = sqrtf(red[0] * (1.0f/(DD-1)));
    y[row*DD + d] = a[d]*diff/(stdv + 1e-6f) + b[d];
}

// ---------------- elementwise epilogues ----------------
__device__ __forceinline__ float gelu_f(float x) {
    const float c = 0.7978845608028654f;   // sqrt(2/pi)
    float x3 = x*x*x;
    return 0.5f*x*(1.0f + tanhf(c*(x + 0.044715f*x3)));
}

__global__ void gelu_kernel(float* __restrict__ x, int n4) {
    int i = blockIdx.x*blockDim.x + threadIdx.x;
    if (i < n4) {
        float4 v = ((float4*)x)[i];
        v.x = gelu_f(v.x); v.y = gelu_f(v.y); v.z = gelu_f(v.z); v.w = gelu_f(v.w);
        ((float4*)x)[i] = v;
    }
}

__global__ void add_kernel(float* __restrict__ h, const float* __restrict__ t, int n4) {
    int i = blockIdx.x*blockDim.x + threadIdx.x;
    if (i < n4) {
        float4 a = ((float4*)h)[i];
        float4 b = ((const float4*)t)[i];
        a.x += b.x; a.y += b.y; a.z += b.z; a.w += b.w;
        ((float4*)h)[i] = a;
    }
}

// ---------------- TF32 WMMA GEMM: C[M,N] = A[M,K] @ W[N,K]^T + bias ----------------
// Block tile 128x128, 8 warps in 2(M) x 4(N), warp tile 64x32, BK=16.
#define BKT  16
#define LDS_ 20

__device__ __forceinline__ void gemm_body(const float* __restrict__ A,
                                          const float* __restrict__ W,
                                          const float* __restrict__ bias,
                                          float* __restrict__ C,
                                          int N, int K, int row0, int col0)
{
    __shared__ float As[128*LDS_];
    __shared__ float Ws[128*LDS_];
    __shared__ float stage[8][16*16];

    int tid  = threadIdx.x;
    int warp = tid >> 5;
    int lane = tid & 31;
    int wm = warp & 1;      // 0..1 -> which 64-row half
    int wn = warp >> 1;     // 0..3 -> which 32-col quarter

    wmma::fragment<wmma::accumulator,16,16,8,float> acc[4][2];
    #pragma unroll
    for (int i = 0; i < 4; i++)
        #pragma unroll
        for (int j = 0; j < 2; j++) wmma::fill_fragment(acc[i][j], 0.0f);

    int lrow = tid >> 1;          // 0..127
    int lcol = (tid & 1) * 8;     // 0 or 8
    const float* Ag = A + (size_t)(row0 + lrow)*K + lcol;
    int wrow = col0 + lrow;
    const float* Wg = W + (size_t)wrow*K + lcol;
    bool wv = wrow < N;
    float* asp = As + lrow*LDS_ + lcol;
    float* wsp = Ws + lrow*LDS_ + lcol;

    for (int kk = 0; kk < K; kk += BKT) {
        float4 a0 = *(const float4*)(Ag + kk);
        float4 a1 = *(const float4*)(Ag + kk + 4);
        asp[0] = wmma::__float_to_tf32(a0.x); asp[1] = wmma::__float_to_tf32(a0.y);
        asp[2] = wmma::__float_to_tf32(a0.z); asp[3] = wmma::__float_to_tf32(a0.w);
        asp[4] = wmma::__float_to_tf32(a1.x); asp[5] = wmma::__float_to_tf32(a1.y);
        asp[6] = wmma::__float_to_tf32(a1.z); asp[7] = wmma::__float_to_tf32(a1.w);
        float4 w0 = wv ? *(const float4*)(Wg + kk)     : make_float4(0.f,0.f,0.f,0.f);
        float4 w1 = wv ? *(const float4*)(Wg + kk + 4) : make_float4(0.f,0.f,0.f,0.f);
        wsp[0] = wmma::__float_to_tf32(w0.x); wsp[1] = wmma::__float_to_tf32(w0.y);
        wsp[2] = wmma::__float_to_tf32(w0.z); wsp[3] = wmma::__float_to_tf32(w0.w);
        wsp[4] = wmma::__float_to_tf32(w1.x); wsp[5] = wmma::__float_to_tf32(w1.y);
        wsp[6] = wmma::__float_to_tf32(w1.z); wsp[7] = wmma::__float_to_tf32(w1.w);
        __syncthreads();
        #pragma unroll
        for (int ks = 0; ks < BKT; ks += 8) {
            wmma::fragment<wmma::matrix_a,16,16,8,wmma::precision::tf32,wmma::row_major> af[4];
            wmma::fragment<wmma::matrix_b,16,16,8,wmma::precision::tf32,wmma::col_major> bf[2];
            #pragma unroll
            for (int i = 0; i < 4; i++)
                wmma::load_matrix_sync(af[i], As + (wm*64 + i*16)*LDS_ + ks, LDS_);
            #pragma unroll
            for (int j = 0; j < 2; j++)
                wmma::load_matrix_sync(bf[j], Ws + (wn*32 + j*16)*LDS_ + ks, LDS_);
            #pragma unroll
            for (int i = 0; i < 4; i++)
                #pragma unroll
                for (int j = 0; j < 2; j++)
                    wmma::mma_sync(acc[i][j], af[i], bf[j], acc[i][j]);
        }
        __syncthreads();
    }

    // epilogue: stage each 16x16 fragment through smem, add bias, guard columns
    float* st = stage[warp];
    int r  = lane >> 1;
    int c0 = (lane & 1) * 8;
    #pragma unroll
    for (int i = 0; i < 4; i++) {
        #pragma unroll
        for (int j = 0; j < 2; j++) {
            wmma::store_matrix_sync(st, acc[i][j], 16, wmma::mem_row_major);
            __syncwarp();
            int grow  = row0 + wm*64 + i*16 + r;
            int gcolb = col0 + wn*32 + j*16 + c0;
            #pragma unroll
            for (int c = 0; c < 8; c++) {
                int gc = gcolb + c;
                if (gc < N) C[(size_t)grow*N + gc] = st[r*16 + c0 + c] + bias[gc];
            }
            __syncwarp();
        }
    }
}

__global__ void __launch_bounds__(256) gemm_tf32(const float* __restrict__ A,
                                                 const float* __restrict__ W,
                                                 const float* __restrict__ bias,
                                                 float* __restrict__ C, int N, int K)
{
    gemm_body(A, W, bias, C, N, K, blockIdx.y*128, blockIdx.x*128);
}

__global__ void __launch_bounds__(256) qktv_gemm(const float* __restrict__ hn,
                                                 const float* __restrict__ temb,
                                                 const float* __restrict__ Wq, const float* __restrict__ Wk,
                                                 const float* __restrict__ Wt, const float* __restrict__ Wv,
                                                 const float* __restrict__ bq, const float* __restrict__ bk,
                                                 const float* __restrict__ bt, const float* __restrict__ bv,
                                                 float* __restrict__ q, float* __restrict__ k1,
                                                 float* __restrict__ k2, float* __restrict__ v)
{
    int z = blockIdx.z;
    const float* A = (z == 2) ? temb : hn;
    const float* W = (z == 0) ? Wq : (z == 1) ? Wk : (z == 2) ? Wt : Wv;
    const float* b = (z == 0) ? bq : (z == 1) ? bk : (z == 2) ? bt : bv;
    float*       C = (z == 0) ? q  : (z == 1) ? k1 : (z == 2) ? k2 : v;
    gemm_body(A, W, b, C, DD, DD, blockIdx.y*128, blockIdx.x*128);
}

// ---------------- attention: one block per (b,h) ----------------
__global__ void attn_kernel(const float* __restrict__ q, const float* __restrict__ k1,
                            const float* __restrict__ k2, const float* __restrict__ v,
                            const int* __restrict__ x, const float* __restrict__ ml,
                            float* __restrict__ ctx)
{
    extern __shared__ float sm[];
    float* qs  = sm;                 // 6400
    float* k1s = qs  + SS*DK_;
    float* k2s = k1s + SS*DK_;
    float* vs  = k2s + SS*DK_;
    float* sc  = vs  + SS*DK_;       // 10000
    int*  keep = (int*)(sc + SS*SS); // 100
    int h = blockIdx.x, b = blockIdx.y;
    int tid = threadIdx.x;
    int base = b*SS*DD + h*DK_;

    for (int idx = tid; idx < SS*DK_; idx += blockDim.x) {
        int s = idx >> 6, d = idx & 63;
        int gi = base + s*DD + d;
        qs[idx] = q[gi]; k1s[idx] = k1[gi]; k2s[idx] = k2[gi]; vs[idx] = v[gi];
    }
    if (tid < SS) keep[tid] = (x[b*SS + tid] > 0) ? 1 : 0;
    __syncthreads();

    if (tid < SS) {
        const float scale = 0.125f;  // 1/sqrt(64)
        const float* qp = qs + tid*DK_;
        float* scrow = sc + tid*SS;
        float mx = -1e30f;
        for (int k = 0; k < SS; k++) {
            const float* p1 = k1s + k*DK_;
            const float* p2 = k2s + k*DK_;
            float s1 = 0.f, s2 = 0.f;
            #pragma unroll 16
            for (int d = 0; d < DK_; d++) { s1 += qp[d]*p1[d]; s2 += qp[d]*p2[d]; }
            // masked_fill BEFORE adding time-scores (exact reference semantics)
            float s = (keep[k] ? s1*scale : -1e9f) + s2*scale;
            scrow[k] = s;
            mx = fmaxf(mx, s);
        }
        float sum = 0.f;
        for (int k = 0; k < SS; k++) { float e = expf(scrow[k] - mx); scrow[k] = e; sum += e; }
        float inv = 1.0f / sum;
        for (int k = 0; k < SS; k++) {
            float z = ml[tid*SS + k];
            float sg = 1.0f / (1.0f + expf(-z));
            scrow[k] *= inv * sg;
        }
        for (int d = 0; d < DK_; d++) {
            float acc = 0.f;
            for (int k = 0; k < SS; k++) acc += scrow[k] * vs[k*DK_ + d];
            ctx[base + tid*DD + d] = acc;
        }
    }
}

// ---------------- host launcher ----------------
extern "C" void kernel_launch(void* const* d_in, const int* in_sizes, int n_in,
                              void* d_out, int out_size)
{
    (void)in_sizes; (void)n_in; (void)out_size;
    const int*   x         = (const int*)  d_in[0];
    const float* times     = (const float*)d_in[1];
    const float* token_emb = (const float*)d_in[2];
    const float* pos_emb   = (const float*)d_in[3];
    const float* sel_w     = (const float*)d_in[4];
    const float* sel_b     = (const float*)d_in[5];
    const float* time_w    = (const float*)d_in[6];
    const float* time_b    = (const float*)d_in[7];
    const float* per_w     = (const float*)d_in[8];
    const float* per_b     = (const float*)d_in[9];
    const float* Wq        = (const float*)d_in[10];
    const float* Wk        = (const float*)d_in[11];
    const float* Wt        = (const float*)d_in[12];
    const float* Wv        = (const float*)d_in[13];
    const float* Wo        = (const float*)d_in[14];
    const float* bq        = (const float*)d_in[15];
    const float* bk        = (const float*)d_in[16];
    const float* bt        = (const float*)d_in[17];
    const float* bv        = (const float*)d_in[18];
    const float* bo        = (const float*)d_in[19];
    const float* mask_log  = (const float*)d_in[20];
    const float* ln1_a     = (const float*)d_in[21];
    const float* ln1_b     = (const float*)d_in[22];
    const float* ln2_a     = (const float*)d_in[23];
    const float* ln2_b     = (const float*)d_in[24];
    const float* ffn_w1    = (const float*)d_in[25];
    const float* ffn_b1    = (const float*)d_in[26];
    const float* ffn_w2    = (const float*)d_in[27];
    const float* ffn_b2    = (const float*)d_in[28];
    const float* out_w     = (const float*)d_in[29];
    const float* out_b     = (const float*)d_in[30];
    float* out = (float*)d_out;

    float *ph,*ptemb,*phn,*pq,*pk1,*pk2,*pv,*pctx,*pffn,*ptmp;
    cudaGetSymbolAddress((void**)&ph,    g_h);
    cudaGetSymbolAddress((void**)&ptemb, g_temb);
    cudaGetSymbolAddress((void**)&phn,   g_hn);
    cudaGetSymbolAddress((void**)&pq,    g_q);
    cudaGetSymbolAddress((void**)&pk1,   g_k1);
    cudaGetSymbolAddress((void**)&pk2,   g_k2);
    cudaGetSymbolAddress((void**)&pv,    g_v);
    cudaGetSymbolAddress((void**)&pctx,  g_ctx);
    cudaGetSymbolAddress((void**)&pffn,  g_ffn);
    cudaGetSymbolAddress((void**)&ptmp,  g_tmp);

    const int attn_smem = (SS*DK_*4 + SS*SS)*(int)sizeof(float) + SS*(int)sizeof(int); // 142,800 B
    cudaFuncSetAttribute(attn_kernel, cudaFuncAttributeMaxDynamicSharedMemorySize, attn_smem);

    embed_kernel<<<MM, 256>>>(x, times, token_emb, pos_emb, sel_w, sel_b,
                              time_w, time_b, per_w, per_b);

    dim3 gD(2, 25);            // N=256
    dim3 gF(8, 25);            // N=1024
    dim3 gQKTV(2, 25, 4);      // 4 fused projections
    const int n4D = MM*DD/4, n4F = MM*DFF_/4;
    for (int l = 0; l < LL; l++) {
        ln_kernel<<<MM, 256>>>(ph, ln1_a + l*DD, ln1_b + l*DD, phn);
        qktv_gemm<<<gQKTV, 256>>>(phn, ptemb,
                                  Wq + (size_t)l*DD*DD, Wk + (size_t)l*DD*DD,
                                  Wt + (size_t)l*DD*DD, Wv + (size_t)l*DD*DD,
                                  bq + l*DD, bk + l*DD, bt + l*DD, bv + l*DD,
                                  pq, pk1, pk2, pv);
        attn_kernel<<<dim3(HH, BB), 128, attn_smem>>>(pq, pk1, pk2, pv, x,
                                                      mask_log + l*SS*SS, pctx);
        gemm_tf32<<<gD, 256>>>(pctx, Wo + (size_t)l*DD*DD, bo + l*DD, ptmp, DD, DD);
        add_kernel<<<(n4D+255)/256, 256>>>(ph, ptmp, n4D);
        ln_kernel<<<MM, 256>>>(ph, ln2_a + l*DD, ln2_b + l*DD, phn);
        gemm_tf32<<<gF, 256>>>(phn, ffn_w1 + (size_t)l*DFF_*DD, ffn_b1 + l*DFF_, pffn, DFF_, DD);
        gelu_kernel<<<(n4F+255)/256, 256>>>(pffn, n4F);
        gemm_tf32<<<gD, 256>>>(pffn, ffn_w2 + (size_t)l*DD*DFF_, ffn_b2 + l*DD, ptmp, DD, DFF_);
        add_kernel<<<(n4D+255)/256, 256>>>(ph, ptmp, n4D);
    }
    gemm_tf32<<<dim3(391, 25), 256>>>(ph, out_w, out_b, out, NOUT, DD);
}

// round 3
// speedup vs baseline: 1.6245x; 1.2715x over previous
#include <cuda_runtime.h>
#include <mma.h>
#include <math.h>
using namespace nvcuda;

// Problem constants
#define BB   32
#define SS   100
#define DD   256
#define HH   4
#define DK_  64
#define LL   3
#define MM   (BB*SS)      // 3200
#define DFF_ 1024
#define NOUT 50001

// ---------------- scratch (no allocation allowed -> device globals) ----------------
__device__ float g_h[MM*DD];
__device__ float g_temb[MM*DD];
__device__ float g_hn[MM*DD];
__device__ float g_q[MM*DD];
__device__ float g_k1[MM*DD];
__device__ float g_k2[MM*DD];
__device__ float g_v[MM*DD];
__device__ float g_ctx[MM*DD];
__device__ float g_ffn[MM*DFF_];

// ---------------- embedding + time embedding ----------------
__global__ void embed_kernel(const int* __restrict__ x, const float* __restrict__ times,
                             const float* __restrict__ token_emb, const float* __restrict__ pos_emb,
                             const float* __restrict__ sel_w, const float* __restrict__ sel_b,
                             const float* __restrict__ time_w, const float* __restrict__ time_b,
                             const float* __restrict__ per_w, const float* __restrict__ per_b)
{
    int bs = blockIdx.x;           // 0..3199
    int s  = bs % SS;
    int d  = threadIdx.x;          // 0..255
    __shared__ float g[64];
    float tval = times[bs];
    if (d < 64) {
        float t = tval * (1.0f/180.0f) * sel_w[d] + sel_b[d];
        g[d] = 1.0f - tanhf(t*t);
    }
    __syncthreads();
    float ang = 2.0f * 3.14159265358979323846f * tval / 24.0f;
    float sa = sinf(ang), ca = cosf(ang);
    float feat = time_b[d];
    const float* tw = time_w + d*64;
    #pragma unroll 16
    for (int j = 0; j < 64; j++) feat += g[j] * tw[j];
    float per = sa*per_w[d*2+0] + ca*per_w[d*2+1] + per_b[d];
    g_temb[bs*DD + d] = feat + per;
    int tok = x[bs];
    g_h[bs*DD + d] = token_emb[(size_t)tok*DD + d] + pos_emb[s*DD + d];
}

// ---------------- LayerNorm (torch variant: unbiased std, eps added to std) ----------------
__global__ void ln_kernel(const float* __restrict__ x, const float* __restrict__ a,
                          const float* __restrict__ b, float* __restrict__ y)
{
    int row = blockIdx.x;
    int d = threadIdx.x;
    int lane = d & 31, warp = d >> 5;
    __shared__ float ws1[8], ws2[8];
    float v = x[row*DD + d];
    float s = v;
    #pragma unroll
    for (int o = 16; o > 0; o >>= 1) s += __shfl_xor_sync(0xffffffff, s, o);
    if (lane == 0) ws1[warp] = s;
    __syncthreads();
    float tot = 0.f;
    #pragma unroll
    for (int i = 0; i < 8; i++) tot += ws1[i];
    float mean = tot * (1.0f/DD);
    float diff = v - mean;
    float s2 = diff*diff;
    #pragma unroll
    for (int o = 16; o > 0; o >>= 1) s2 += __shfl_xor_sync(0xffffffff, s2, o);
    if (lane == 0) ws2[warp] = s2;
    __syncthreads();
    float tot2 = 0.f;
    #pragma unroll
    for (int i = 0; i < 8; i++) tot2 += ws2[i];
    float stdv = sqrtf(tot2 * (1.0f/(DD-1)));
    y[row*DD + d] = a[d]*diff/(stdv + 1e-6f) + b[d];
}

// ---------------- GELU ----------------
__device__ __forceinline__ float gelu_f(float x) {
    const float c = 0.7978845608028654f;   // sqrt(2/pi)
    float x3 = x*x*x;
    return 0.5f*x*(1.0f + tanhf(c*(x + 0.044715f*x3)));
}

// ---------------- TF32 WMMA GEMM: C[M,N] = A[M,K] @ W[N,K]^T + bias ----------------
// Block tile 128x128, 8 warps in 2(M) x 4(N), warp tile 64x32, BK=16, double-buffered.
// epi: 0 = none, 1 = gelu, 2 = += res
#define BKT  16
#define LDS_ 20

__device__ __forceinline__ void gemm_body(const float* __restrict__ A,
                                          const float* __restrict__ W,
                                          const float* __restrict__ bias,
                                          const float* __restrict__ res,
                                          float* __restrict__ C,
                                          int N, int K, int row0, int col0, int epi)
{
    __shared__ float As[2][128*LDS_];
    __shared__ float Ws[2][128*LDS_];
    __shared__ float stage[8][16*16];

    int tid  = threadIdx.x;
    int warp = tid >> 5;
    int lane = tid & 31;
    int wm = warp & 1;      // 0..1 -> which 64-row half
    int wn = warp >> 1;     // 0..3 -> which 32-col quarter

    wmma::fragment<wmma::accumulator,16,16,8,float> acc[4][2];
    #pragma unroll
    for (int i = 0; i < 4; i++)
        #pragma unroll
        for (int j = 0; j < 2; j++) wmma::fill_fragment(acc[i][j], 0.0f);

    int lrow = tid >> 1;          // 0..127
    int lcol = (tid & 1) * 8;     // 0 or 8
    const float* Ag = A + (size_t)(row0 + lrow)*K + lcol;
    int wrow = col0 + lrow;
    const float* Wg = W + (size_t)wrow*K + lcol;
    bool wv = wrow < N;

    float* asp0 = &As[0][lrow*LDS_ + lcol];
    float* wsp0 = &Ws[0][lrow*LDS_ + lcol];
    float* asp1 = &As[1][lrow*LDS_ + lcol];
    float* wsp1 = &Ws[1][lrow*LDS_ + lcol];

    // prologue: load k-tile 0 into buffer 0
    {
        float4 a0 = *(const float4*)(Ag);
        float4 a1 = *(const float4*)(Ag + 4);
        float4 w0 = wv ? *(const float4*)(Wg)     : make_float4(0.f,0.f,0.f,0.f);
        float4 w1 = wv ? *(const float4*)(Wg + 4) : make_float4(0.f,0.f,0.f,0.f);
        float4 ca0 = make_float4(wmma::__float_to_tf32(a0.x), wmma::__float_to_tf32(a0.y),
                                 wmma::__float_to_tf32(a0.z), wmma::__float_to_tf32(a0.w));
        float4 ca1 = make_float4(wmma::__float_to_tf32(a1.x), wmma::__float_to_tf32(a1.y),
                                 wmma::__float_to_tf32(a1.z), wmma::__float_to_tf32(a1.w));
        float4 cw0 = make_float4(wmma::__float_to_tf32(w0.x), wmma::__float_to_tf32(w0.y),
                                 wmma::__float_to_tf32(w0.z), wmma::__float_to_tf32(w0.w));
        float4 cw1 = make_float4(wmma::__float_to_tf32(w1.x), wmma::__float_to_tf32(w1.y),
                                 wmma::__float_to_tf32(w1.z), wmma::__float_to_tf32(w1.w));
        *(float4*)(asp0)     = ca0; *(float4*)(asp0 + 4) = ca1;
        *(float4*)(wsp0)     = cw0; *(float4*)(wsp0 + 4) = cw1;
    }
    __syncthreads();

    int buf = 0;
    for (int kk = BKT; kk <= K; kk += BKT) {
        float4 na0, na1, nw0, nw1;
        bool more = (kk < K);
        if (more) {
            na0 = *(const float4*)(Ag + kk);
            na1 = *(const float4*)(Ag + kk + 4);
            nw0 = wv ? *(const float4*)(Wg + kk)     : make_float4(0.f,0.f,0.f,0.f);
            nw1 = wv ? *(const float4*)(Wg + kk + 4) : make_float4(0.f,0.f,0.f,0.f);
        }
        const float* Ab = &As[buf][0];
        const float* Wb = &Ws[buf][0];
        #pragma unroll
        for (int ks = 0; ks < BKT; ks += 8) {
            wmma::fragment<wmma::matrix_a,16,16,8,wmma::precision::tf32,wmma::row_major> af[4];
            wmma::fragment<wmma::matrix_b,16,16,8,wmma::precision::tf32,wmma::col_major> bf[2];
            #pragma unroll
            for (int i = 0; i < 4; i++)
                wmma::load_matrix_sync(af[i], Ab + (wm*64 + i*16)*LDS_ + ks, LDS_);
            #pragma unroll
            for (int j = 0; j < 2; j++)
                wmma::load_matrix_sync(bf[j], Wb + (wn*32 + j*16)*LDS_ + ks, LDS_);
            #pragma unroll
            for (int i = 0; i < 4; i++)
                #pragma unroll
                for (int j = 0; j < 2; j++)
                    wmma::mma_sync(acc[i][j], af[i], bf[j], acc[i][j]);
        }
        if (more) {
            float* ad = buf ? asp0 : asp1;
            float* wd = buf ? wsp0 : wsp1;
            float4 ca0 = make_float4(wmma::__float_to_tf32(na0.x), wmma::__float_to_tf32(na0.y),
                                     wmma::__float_to_tf32(na0.z), wmma::__float_to_tf32(na0.w));
            float4 ca1 = make_float4(wmma::__float_to_tf32(na1.x), wmma::__float_to_tf32(na1.y),
                                     wmma::__float_to_tf32(na1.z), wmma::__float_to_tf32(na1.w));
            float4 cw0 = make_float4(wmma::__float_to_tf32(nw0.x), wmma::__float_to_tf32(nw0.y),
                                     wmma::__float_to_tf32(nw0.z), wmma::__float_to_tf32(nw0.w));
            float4 cw1 = make_float4(wmma::__float_to_tf32(nw1.x), wmma::__float_to_tf32(nw1.y),
                                     wmma::__float_to_tf32(nw1.z), wmma::__float_to_tf32(nw1.w));
            *(float4*)(ad)     = ca0; *(float4*)(ad + 4) = ca1;
            *(float4*)(wd)     = cw0; *(float4*)(wd + 4) = cw1;
            __syncthreads();
            buf ^= 1;
        }
    }

    // epilogue: stage each 16x16 fragment through smem, add bias, epi, guard columns
    float* st = stage[warp];
    int r  = lane >> 1;
    int c0 = (lane & 1) * 8;
    #pragma unroll
    for (int i = 0; i < 4; i++) {
        #pragma unroll
        for (int j = 0; j < 2; j++) {
            wmma::store_matrix_sync(st, acc[i][j], 16, wmma::mem_row_major);
            __syncwarp();
            int grow  = row0 + wm*64 + i*16 + r;
            int gcolb = col0 + wn*32 + j*16 + c0;
            #pragma unroll
            for (int c = 0; c < 8; c++) {
                int gc = gcolb + c;
                if (gc < N) {
                    float v = st[r*16 + c0 + c] + bias[gc];
                    if (epi == 1) v = gelu_f(v);
                    else if (epi == 2) v += res[(size_t)grow*N + gc];
                    C[(size_t)grow*N + gc] = v;
                }
            }
            __syncwarp();
        }
    }
}

__global__ void __launch_bounds__(256) gemm_tf32(const float* __restrict__ A,
                                                 const float* __restrict__ W,
                                                 const float* __restrict__ bias,
                                                 const float* __restrict__ res,
                                                 float* __restrict__ C, int N, int K, int epi)
{
    gemm_body(A, W, bias, res, C, N, K, blockIdx.y*128, blockIdx.x*128, epi);
}

__global__ void __launch_bounds__(256) qktv_gemm(const float* __restrict__ hn,
                                                 const float* __restrict__ temb,
                                                 const float* __restrict__ Wq, const float* __restrict__ Wk,
                                                 const float* __restrict__ Wt, const float* __restrict__ Wv,
                                                 const float* __restrict__ bq, const float* __restrict__ bk,
                                                 const float* __restrict__ bt, const float* __restrict__ bv,
                                                 float* __restrict__ q, float* __restrict__ k1,
                                                 float* __restrict__ k2, float* __restrict__ v)
{
    int z = blockIdx.z;
    const float* A = (z == 2) ? temb : hn;
    const float* W = (z == 0) ? Wq : (z == 1) ? Wk : (z == 2) ? Wt : Wv;
    const float* b = (z == 0) ? bq : (z == 1) ? bk : (z == 2) ? bt : bv;
    float*       C = (z == 0) ? q  : (z == 1) ? k1 : (z == 2) ? k2 : v;
    gemm_body(A, W, b, nullptr, C, DD, DD, blockIdx.y*128, blockIdx.x*128, 0);
}

// ---------------- attention: one block per (b,h), 256 threads, 3 phases ----------------
#define KTP 104   // padded pitch for transposed K tiles

__global__ void __launch_bounds__(256) attn_kernel(
        const float* __restrict__ q, const float* __restrict__ k1,
        const float* __restrict__ k2, const float* __restrict__ v,
        const int* __restrict__ x, const float* __restrict__ ml,
        float* __restrict__ ctx)
{
    extern __shared__ float sm[];
    float* qs  = sm;                     // 100*64
    float* vs  = qs  + SS*DK_;           // 100*64
    float* k1t = vs  + SS*DK_;           // 64*104 (transposed)
    float* k2t = k1t + DK_*KTP;          // 64*104
    float* sc  = k2t + DK_*KTP;          // 100*100
    int*  keep = (int*)(sc + SS*SS);     // 100
    int h = blockIdx.x, b = blockIdx.y;
    int tid = threadIdx.x;
    int lane = tid & 31, warp = tid >> 5;
    int base = b*SS*DD + h*DK_;

    for (int idx = tid; idx < SS*DK_; idx += 256) {
        int s = idx >> 6, d = idx & 63;
        int gi = base + s*DD + d;
        qs[idx] = q[gi];
        vs[idx] = v[gi];
        k1t[d*KTP + s] = k1[gi];
        k2t[d*KTP + s] = k2[gi];
    }
    if (tid < SS) keep[tid] = (x[b*SS + tid] > 0) ? 1 : 0;
    __syncthreads();

    // Phase A: scores. Each thread computes a 1q x 4k group.
    const float scale = 0.125f;  // 1/sqrt(64)
    for (int g = tid; g < SS*25; g += 256) {
        int qi = g / 25;
        int kg = (g - qi*25) * 4;
        const float* qp = qs + qi*DK_;
        float4 s1 = make_float4(0.f,0.f,0.f,0.f);
        float4 s2 = make_float4(0.f,0.f,0.f,0.f);
        #pragma unroll 8
        for (int d = 0; d < DK_; d++) {
            float qv = qp[d];
            float4 b1 = *(const float4*)(k1t + d*KTP + kg);
            float4 b2 = *(const float4*)(k2t + d*KTP + kg);
            s1.x += qv*b1.x; s1.y += qv*b1.y; s1.z += qv*b1.z; s1.w += qv*b1.w;
            s2.x += qv*b2.x; s2.y += qv*b2.y; s2.z += qv*b2.z; s2.w += qv*b2.w;
        }
        // masked_fill BEFORE adding time-scores (exact reference semantics)
        float* sr = sc + qi*SS + kg;
        const int* kp = keep + kg;
        sr[0] = (kp[0] ? s1.x*scale : -1e9f) + s2.x*scale;
        sr[1] = (kp[1] ? s1.y*scale : -1e9f) + s2.y*scale;
        sr[2] = (kp[2] ? s1.z*scale : -1e9f) + s2.z*scale;
        sr[3] = (kp[3] ? s1.w*scale : -1e9f) + s2.w*scale;
    }
    __syncthreads();

    // Phase B: softmax per row * sigmoid(mask_logits), warp per row
    for (int r = warp; r < SS; r += 8) {
        float* row = sc + r*SS;
        float mx = -1e30f;
        for (int c = lane; c < SS; c += 32) mx = fmaxf(mx, row[c]);
        #pragma unroll
        for (int o = 16; o > 0; o >>= 1) mx = fmaxf(mx, __shfl_xor_sync(0xffffffff, mx, o));
        float sum = 0.f;
        for (int c = lane; c < SS; c += 32) {
            float e = __expf(row[c] - mx);
            row[c] = e; sum += e;
        }
        #pragma unroll
        for (int o = 16; o > 0; o >>= 1) sum += __shfl_xor_sync(0xffffffff, sum, o);
        float inv = 1.0f / sum;
        const float* mlr = ml + r*SS;
        for (int c = lane; c < SS; c += 32) {
            float z = mlr[c];
            float sg = 1.0f / (1.0f + __expf(-z));
            row[c] *= inv * sg;
        }
    }
    __syncthreads();

    // Phase C: ctx = p @ V, float4 over d
    for (int o = tid; o < SS*16; o += 256) {
        int qi = o >> 4;
        int dg = (o & 15) * 4;
        const float* sr = sc + qi*SS;
        const float* vp = vs + dg;
        float4 a = make_float4(0.f,0.f,0.f,0.f);
        #pragma unroll 4
        for (int k = 0; k < SS; k++) {
            float p = sr[k];
            float4 vv = *(const float4*)(vp + k*DK_);
            a.x += p*vv.x; a.y += p*vv.y; a.z += p*vv.z; a.w += p*vv.w;
        }
        *(float4*)(ctx + base + qi*DD + dg) = a;
    }
}

// ---------------- host launcher ----------------
extern "C" void kernel_launch(void* const* d_in, const int* in_sizes, int n_in,
                              void* d_out, int out_size)
{
    (void)in_sizes; (void)n_in; (void)out_size;
    const int*   x         = (const int*)  d_in[0];
    const float* times     = (const float*)d_in[1];
    const float* token_emb = (const float*)d_in[2];
    const float* pos_emb   = (const float*)d_in[3];
    const float* sel_w     = (const float*)d_in[4];
    const float* sel_b     = (const float*)d_in[5];
    const float* time_w    = (const float*)d_in[6];
    const float* time_b    = (const float*)d_in[7];
    const float* per_w     = (const float*)d_in[8];
    const float* per_b     = (const float*)d_in[9];
    const float* Wq        = (const float*)d_in[10];
    const float* Wk        = (const float*)d_in[11];
    const float* Wt        = (const float*)d_in[12];
    const float* Wv        = (const float*)d_in[13];
    const float* Wo        = (const float*)d_in[14];
    const float* bq        = (const float*)d_in[15];
    const float* bk        = (const float*)d_in[16];
    const float* bt        = (const float*)d_in[17];
    const float* bv        = (const float*)d_in[18];
    const float* bo        = (const float*)d_in[19];
    const float* mask_log  = (const float*)d_in[20];
    const float* ln1_a     = (const float*)d_in[21];
    const float* ln1_b     = (const float*)d_in[22];
    const float* ln2_a     = (const float*)d_in[23];
    const float* ln2_b     = (const float*)d_in[24];
    const float* ffn_w1    = (const float*)d_in[25];
    const float* ffn_b1    = (const float*)d_in[26];
    const float* ffn_w2    = (const float*)d_in[27];
    const float* ffn_b2    = (const float*)d_in[28];
    const float* out_w     = (const float*)d_in[29];
    const float* out_b     = (const float*)d_in[30];
    float* out = (float*)d_out;

    float *ph,*ptemb,*phn,*pq,*pk1,*pk2,*pv,*pctx,*pffn;
    cudaGetSymbolAddress((void**)&ph,    g_h);
    cudaGetSymbolAddress((void**)&ptemb, g_temb);
    cudaGetSymbolAddress((void**)&phn,   g_hn);
    cudaGetSymbolAddress((void**)&pq,    g_q);
    cudaGetSymbolAddress((void**)&pk1,   g_k1);
    cudaGetSymbolAddress((void**)&pk2,   g_k2);
    cudaGetSymbolAddress((void**)&pv,    g_v);
    cudaGetSymbolAddress((void**)&pctx,  g_ctx);
    cudaGetSymbolAddress((void**)&pffn,  g_ffn);

    const int attn_smem = (SS*DK_*2 + DK_*KTP*2 + SS*SS)*(int)sizeof(float)
                        + SS*(int)sizeof(int);   // ~144.8 KB
    cudaFuncSetAttribute(attn_kernel, cudaFuncAttributeMaxDynamicSharedMemorySize, attn_smem);

    embed_kernel<<<MM, 256>>>(x, times, token_emb, pos_emb, sel_w, sel_b,
                              time_w, time_b, per_w, per_b);

    dim3 gD(2, 25);            // N=256
    dim3 gF(8, 25);            // N=1024
    dim3 gQKTV(2, 25, 4);      // 4 fused projections
    for (int l = 0; l < LL; l++) {
        ln_kernel<<<MM, 256>>>(ph, ln1_a + l*DD, ln1_b + l*DD, phn);
        qktv_gemm<<<gQKTV, 256>>>(phn, ptemb,
                                  Wq + (size_t)l*DD*DD, Wk + (size_t)l*DD*DD,
                                  Wt + (size_t)l*DD*DD, Wv + (size_t)l*DD*DD,
                                  bq + l*DD, bk + l*DD, bt + l*DD, bv + l*DD,
                                  pq, pk1, pk2, pv);
        attn_kernel<<<dim3(HH, BB), 256, attn_smem>>>(pq, pk1, pk2, pv, x,
                                                      mask_log + l*SS*SS, pctx);
        gemm_tf32<<<gD, 256>>>(pctx, Wo + (size_t)l*DD*DD, bo + l*DD, ph, ph, DD, DD, 2);
        ln_kernel<<<MM, 256>>>(ph, ln2_a + l*DD, ln2_b + l*DD, phn);
        gemm_tf32<<<gF, 256>>>(phn, ffn_w1 + (size_t)l*DFF_*DD, ffn_b1 + l*DFF_, nullptr, pffn, DFF_, DD, 1);
        gemm_tf32<<<gD, 256>>>(pffn, ffn_w2 + (size_t)l*DD*DFF_, ffn_b2 + l*DD, ph, ph, DD, DFF_, 2);
    }
    gemm_tf32<<<dim3(391, 25), 256>>>(ph, out_w, out_b, nullptr, out, NOUT, DD, 0);
}